// round 6
// baseline (speedup 1.0000x reference)
#include <cuda_runtime.h>
#include <cstdint>

#define B_ 64
#define T_ 1024
#define F_ 128
#define U_ 256

// Scratch for h = inputs @ R, layout [B, T, U]; +U_ pad so the t+1 prefetch
// on the last step never reads out of bounds.
__device__ float g_h[(size_t)B_ * T_ * U_ + U_];

// ---------------- helpers ----------------

__device__ __forceinline__ unsigned smem_u32(const void* p) {
    return (unsigned)__cvta_generic_to_shared(p);
}
__device__ __forceinline__ unsigned long long dup2(float s) {
    unsigned long long r;
    asm("mov.b64 %0, {%1, %1};" : "=l"(r) : "r"(__float_as_uint(s)));
    return r;
}
__device__ __forceinline__ unsigned long long pk2(float lo, float hi) {
    unsigned long long r;
    asm("mov.b64 %0, {%1, %2};" : "=l"(r)
        : "r"(__float_as_uint(lo)), "r"(__float_as_uint(hi)));
    return r;
}
__device__ __forceinline__ unsigned long long ffma2(unsigned long long a, unsigned long long b,
                                                    unsigned long long c) {
    unsigned long long d;
    asm("fma.rn.f32x2 %0, %1, %2, %3;" : "=l"(d) : "l"(a), "l"(b), "l"(c));
    return d;
}
__device__ __forceinline__ unsigned long long fadd2(unsigned long long a, unsigned long long b) {
    unsigned long long d;
    asm("add.rn.f32x2 %0, %1, %2;" : "=l"(d) : "l"(a), "l"(b));
    return d;
}
__device__ __forceinline__ float2 unpk(unsigned long long v) {
    unsigned lo, hi;
    asm("mov.b64 {%0, %1}, %2;" : "=r"(lo), "=r"(hi) : "l"(v));
    return make_float2(__uint_as_float(lo), __uint_as_float(hi));
}
__device__ __forceinline__ unsigned mapa_u32(unsigned addr, unsigned rank) {
    unsigned r;
    asm("mapa.shared::cluster.u32 %0, %1, %2;" : "=r"(r) : "r"(addr), "r"(rank));
    return r;
}
__device__ __forceinline__ void mbar_init(unsigned addr, unsigned cnt) {
    asm volatile("mbarrier.init.shared.b64 [%0], %1;" :: "r"(addr), "r"(cnt) : "memory");
}
__device__ __forceinline__ void mbar_expect_tx(unsigned addr, unsigned bytes) {
    asm volatile("mbarrier.arrive.expect_tx.shared::cta.b64 _, [%0], %1;"
                 :: "r"(addr), "r"(bytes) : "memory");
}
__device__ __forceinline__ void mbar_wait(unsigned addr, unsigned parity) {
    asm volatile(
        "{\n\t"
        ".reg .pred P;\n"
        "WAIT%=:\n\t"
        "mbarrier.try_wait.parity.acquire.cluster.shared::cta.b64 P, [%0], %1, 0x989680;\n\t"
        "@!P bra WAIT%=;\n\t"
        "}"
        :: "r"(addr), "r"(parity) : "memory");
}
__device__ __forceinline__ void bulk_copy_s2s(unsigned dst_cluster, unsigned src_cta,
                                              unsigned bytes, unsigned rbar_cluster) {
    asm volatile(
        "cp.async.bulk.shared::cluster.shared::cta.mbarrier::complete_tx::bytes "
        "[%0], [%1], %2, [%3];"
        :: "r"(dst_cluster), "r"(src_cta), "r"(bytes), "r"(rbar_cluster) : "memory");
}
__device__ __forceinline__ void cluster_sync_() {
    asm volatile("barrier.cluster.arrive.aligned;" ::: "memory");
    asm volatile("barrier.cluster.wait.aligned;" ::: "memory");
}
// accurate tanh: |err| ~1e-6 rel, overflow-free
__device__ __forceinline__ float fast_tanh(float x) {
    float ax = fabsf(x) * -2.885390081777927f;  // -2*log2(e)
    float e;
    asm("ex2.approx.f32 %0, %1;" : "=f"(e) : "f"(ax));
    float num = 1.0f - e;
    float den = 1.0f + e;
    float r;
    asm("rcp.approx.f32 %0, %1;" : "=f"(r) : "f"(den));
    return copysignf(num * r, x);
}

// ---------------- phase 1: h = inputs @ R ----------------
__global__ void __launch_bounds__(256, 1)
proj_kernel(const float* __restrict__ inp, const float* __restrict__ R)
{
    __shared__ __align__(16) unsigned long long in_dupT[128 * 18];  // [f][r] pad 18
    __shared__ __align__(16) unsigned long long partsm[128 * 17];   // pad 17

    const int tid = threadIdx.x;
    const int up = tid & 127;
    const int fh = tid >> 7;

    unsigned long long w[64];
    const unsigned long long* R64 = (const unsigned long long*)R;
#pragma unroll
    for (int j = 0; j < 64; j++)
        w[j] = R64[(64 * fh + j) * 128 + up];

    const int ntiles = (B_ * T_) / 16;
    for (int tile = blockIdx.x; tile < ntiles; tile += gridDim.x) {
        const int row0 = tile * 16;
        __syncthreads();
#pragma unroll
        for (int e = 0; e < 8; e++) {
            int idx = e * 256 + tid;
            int r = idx >> 7, f = idx & 127;
            float v = inp[(size_t)(row0 + r) * F_ + f];
            in_dupT[f * 18 + r] = dup2(v);
        }
        __syncthreads();

        unsigned long long acc[16];
#pragma unroll
        for (int r = 0; r < 16; r++) acc[r] = 0ull;

#pragma unroll
        for (int j = 0; j < 64; j++) {
            const int f = 64 * fh + j;
            const ulonglong2* col = (const ulonglong2*)&in_dupT[f * 18];
#pragma unroll
            for (int rr = 0; rr < 8; rr++) {
                ulonglong2 v = col[rr];
                acc[2 * rr]     = ffma2(v.x, w[j], acc[2 * rr]);
                acc[2 * rr + 1] = ffma2(v.y, w[j], acc[2 * rr + 1]);
            }
        }
        if (fh) {
#pragma unroll
            for (int r = 0; r < 16; r++) partsm[up * 17 + r] = acc[r];
        }
        __syncthreads();
        if (!fh) {
#pragma unroll
            for (int r = 0; r < 16; r++) {
                unsigned long long tot = fadd2(acc[r], partsm[up * 17 + r]);
                float2 o = unpk(tot);
                *(float2*)&g_h[(size_t)(row0 + r) * U_ + 2 * up] = o;
            }
        }
    }
}

// ---------------- phase 2: the recurrence ----------------
// 4-CTA cluster per 2 batches. CTA rank r produces u in [64r, 64r+64) for both
// batches, with FULL K=256 weights register-resident. State lives quarter-major:
// s_q[buf][q][bb][64] so producer q's 512B (both batches) is one contiguous
// bulk-copy. Per step: own-quarter FMAs first (no wait), then tx-mbarrier wait
// for the 3 peer quarters (3 copies x 512B = 1536B expected), peer FMAs,
// kh-shuffle reduce, tanh, STS+STG, one __syncthreads, then 3 bulk copies of
// the fresh quarter to the peers. Double-buffered; the step handshake provides
// buffer backpressure (same proof as the 2-CTA version).
__global__ void __launch_bounds__(256, 1) __cluster_dims__(4, 1, 1)
rnn_kernel(const float* __restrict__ W, const float* __restrict__ bias,
           const float* __restrict__ x0, float* __restrict__ out)
{
    __shared__ __align__(16) float s_q[2][4][2][64];   // [buf][producer q][bb][u]
    __shared__ __align__(8)  unsigned long long mbar[2];

    const int tid = threadIdx.x;
    const int bb = tid >> 7;          // batch within cluster (warps 0-3 / 4-7)
    const int u  = (tid >> 1) & 63;   // local u index
    const int kh = tid & 1;           // k sub-half within each quarter
    unsigned rank;
    asm("mov.u32 %0, %%cluster_ctarank;" : "=r"(rank));
    const int b  = 2 * (blockIdx.x >> 2) + bb;   // my batch
    const int gu = 64 * (int)rank + u;

    // weights for quarters in order q = rank^i (i=0 -> own quarter first)
    // w[i][m] = {W[q*64 + kh*32 + 2m][gu], W[q*64 + kh*32 + 2m + 1][gu]}
    unsigned long long w[4][16];
#pragma unroll
    for (int i = 0; i < 4; i++) {
        int q = (int)rank ^ i;
        int kb = q * 64 + kh * 32;
#pragma unroll
        for (int m = 0; m < 16; m++) {
            int k = kb + 2 * m;
            w[i][m] = pk2(W[(size_t)k * U_ + gu], W[(size_t)(k + 1) * U_ + gu]);
        }
    }

    // init state buffers (buffer 1 = "state at t-1" for t=0)
    for (int i = tid; i < 4 * 2 * 64; i += 256) {
        int q = i >> 7, rest = i & 127;
        (&s_q[1][0][0][0])[i] = x0[q * 64 + (rest & 63)];
    }
    if (tid == 0) {
        mbar_init(smem_u32(&mbar[0]), 1);
        mbar_init(smem_u32(&mbar[1]), 1);
    }
    __syncthreads();
    cluster_sync_();  // mbarriers + x0 visible cluster-wide before any copy

    // per-buffer remote destinations: my quarter slot in each peer's smem,
    // and each peer's mbarrier
    unsigned l_src[2], r_dst[2][3], r_bar[2][3], l_bar[2];
#pragma unroll
    for (int bf = 0; bf < 2; bf++) {
        l_src[bf] = smem_u32(&s_q[bf][rank][0][0]);
        l_bar[bf] = smem_u32(&mbar[bf]);
#pragma unroll
        for (int i = 0; i < 3; i++) {
            unsigned q = rank ^ (unsigned)(i + 1);
            r_dst[bf][i] = mapa_u32(l_src[bf], q);
            r_bar[bf][i] = mapa_u32(l_bar[bf], q);
        }
    }

    const float bias_u = bias[gu];
    const float* hptr = &g_h[((size_t)b * T_) * U_ + gu];
    float hcur = hptr[0];

    for (int t = 0; t < T_; t++) {
        const int prev = (t + 1) & 1;
        const int cur  = t & 1;

        float hnext = hptr[(size_t)(t + 1) * U_];  // pad makes last read safe

        if (t > 0 && tid == 0) mbar_expect_tx(l_bar[prev], 1536u);

        // ---- own quarter (written locally last step; no exchange needed) ----
        unsigned long long a0 = 0ull, a1 = 0ull;
        {
            const ulonglong2* sp = (const ulonglong2*)&s_q[prev][rank][bb][kh * 32];
#pragma unroll
            for (int j = 0; j < 8; j++) {
                ulonglong2 v = sp[j];
                a0 = ffma2(v.x, w[0][2 * j],     a0);
                a1 = ffma2(v.y, w[0][2 * j + 1], a1);
            }
        }

        // ---- wait for the 3 peer quarters (copies issued at end of t-1) ----
        if (t > 0) mbar_wait(l_bar[prev], ((t - 1) >> 1) & 1);

#pragma unroll
        for (int i = 1; i < 4; i++) {
            int q = (int)rank ^ i;
            const ulonglong2* sp = (const ulonglong2*)&s_q[prev][q][bb][kh * 32];
#pragma unroll
            for (int j = 0; j < 8; j++) {
                ulonglong2 v = sp[j];
                a0 = ffma2(v.x, w[i][2 * j],     a0);
                a1 = ffma2(v.y, w[i][2 * j + 1], a1);
            }
        }

        // ---- reduce kh-partials: in-register + 1 butterfly shuffle ----
        float2 aa = unpk(fadd2(a0, a1));
        float s = aa.x + aa.y;
        s += __shfl_xor_sync(0xffffffffu, s, 1);

        float st = fast_tanh(s + hcur + bias_u);
        if (kh == 0) {
            s_q[cur][rank][bb][u] = st;
            out[((size_t)t * B_ + b) * U_ + gu] = st;
        }
        hcur = hnext;

        __syncthreads();  // fresh quarter visible CTA-wide + ordered for copies

        // ---- ship fresh quarter (both batches, 512B) to the 3 peers ----
        if (tid == 0 && t < T_ - 1) {
            asm volatile("fence.proxy.async.shared::cta;" ::: "memory");
            bulk_copy_s2s(r_dst[cur][0], l_src[cur], 512u, r_bar[cur][0]);
            bulk_copy_s2s(r_dst[cur][1], l_src[cur], 512u, r_bar[cur][1]);
            bulk_copy_s2s(r_dst[cur][2], l_src[cur], 512u, r_bar[cur][2]);
        }
    }
    cluster_sync_();  // keep all CTAs alive until cluster traffic lands
}

// ---------------- launch ----------------

extern "C" void kernel_launch(void* const* d_in, const int* in_sizes, int n_in,
                              void* d_out, int out_size)
{
    (void)in_sizes; (void)n_in; (void)out_size;
    const float* inputs = (const float*)d_in[0];  // [B,T,F]
    const float* R      = (const float*)d_in[1];  // [F,U]
    const float* W      = (const float*)d_in[2];  // [U,U]
    const float* bias   = (const float*)d_in[3];  // [U]
    const float* x0     = (const float*)d_in[4];  // [U]
    float* out = (float*)d_out;                   // [T,B,U]

    proj_kernel<<<304, 256>>>(inputs, R);
    rnn_kernel<<<2 * B_, 256>>>(W, bias, x0, out);
}